// round 8
// baseline (speedup 1.0000x reference)
#include <cuda_runtime.h>
#include <cuda_bf16.h>
#include <cstdint>

#define STRD 313
#define OFF_LS   0
#define OFF_RS   14976
#define OFF_COST 32256
#define OFF_P    93632
#define OFF_ENT  155008
#define OFF_PREV 156256
#define OFF_NEXT 157504
#define OFF_SEG  158752
#define OFF_RED  159936
#define SMEM_BYTES 160032

__device__ float g_row[256];
__device__ unsigned g_ticket;

// per-128B-row rotation: 16B-block j -> byte offset. L reads conflict-free,
// R reads <=2-way (vs 7-way with the old XOR swizzle).
__device__ __forceinline__ int rot(int j) {
    return (((j & ~7) | ((j + (j >> 3)) & 7)) << 4);
}

__device__ __forceinline__ void cp16(uint32_t dst, const void* src) {
    asm volatile("cp.async.cg.shared.global [%0], [%1], 16;\n" :: "r"(dst), "l"(src));
}
__device__ __forceinline__ unsigned long long lds64(uint32_t a) {
    unsigned long long v; asm("ld.shared.b64 %0, [%1];" : "=l"(v) : "r"(a)); return v;
}
__device__ __forceinline__ unsigned long long lds64h(uint32_t a) {
    unsigned long long v; asm("ld.shared.b64 %0, [%1+8];" : "=l"(v) : "r"(a)); return v;
}
__device__ __forceinline__ void fma2(unsigned long long& d, unsigned long long a,
                                     unsigned long long b) {
    asm("fma.rn.f32x2 %0, %1, %2, %0;" : "+l"(d) : "l"(a), "l"(b));
}
__device__ __forceinline__ float accsum(unsigned long long v) {
    unsigned lo, hi; asm("mov.b64 {%0,%1}, %2;" : "=r"(lo), "=r"(hi) : "l"(v));
    return __uint_as_float(lo) + __uint_as_float(hi);
}

__device__ __forceinline__ float col_entropy(const float* cost, int x) {
    int dmax = x < 48 ? x : 48;
    const float* c = cost + x;
    float m = c[0];
    for (int d = 1; d <= dmax; d++) m = fmaxf(m, c[d * STRD]);
    float S = 0.f;
    for (int d = 0; d <= dmax; d++) S += expf((c[d * STRD] - m) * 10.0f);
    float logS = logf(S), invS = 1.0f / S;
    float thr = logS - 18.420681f;
    float acc = 0.f;
    for (int d = 0; d <= dmax; d++) {
        float l = (c[d * STRD] - m) * 10.0f;
        if (l >= thr) { float p = expf(l) * invS; acc -= p * (l - logS); }
        else acc += 1.8420681e-7f;
    }
    acc += (float)(48 - dmax) * 1.8420681e-7f;
    if (dmax == 0) return 0.f;
    float e = acc / (logf((float)(dmax + 1)) + 1e-8f);
    return fminf(1.0f, fmaxf(0.0f, e));
}

__device__ __forceinline__ void extents(const float* ent, int* prevv, int* nextv, int tid) {
    int wid = tid >> 5, lane = tid & 31;
    if (wid == 0) {
        int carry = -1;
        for (int s = 0; s < 10; s++) {
            int idx = s * 32 + lane;
            int v = (idx < 312 && ent[idx] <= 0.6f) ? idx : -1;
            #pragma unroll
            for (int o = 1; o < 32; o <<= 1) {
                int t = __shfl_up_sync(0xffffffffu, v, o);
                if (lane >= o) v = max(v, t);
            }
            v = max(v, carry);
            if (idx < 312) prevv[idx] = v;
            carry = __shfl_sync(0xffffffffu, v, 31);
        }
    } else if (wid == 1) {
        int carry = 312;
        for (int s = 0; s < 10; s++) {
            int idx = 311 - (s * 32 + lane);
            int v = (idx >= 0 && ent[idx] <= 0.6f) ? idx : 312;
            #pragma unroll
            for (int o = 1; o < 32; o <<= 1) {
                int t = __shfl_up_sync(0xffffffffu, v, o);
                if (lane >= o) v = min(v, t);
            }
            v = min(v, carry);
            if (idx >= 0) nextv[idx] = v;
            carry = __shfl_sync(0xffffffffu, v, 31);
        }
    }
}

__device__ __forceinline__ void prefix_scan(const float* cost, float* P, float* segS, int tid) {
    int d = tid / 6, seg = tid - d * 6;
    if (tid < 294) {
        int xs = seg * 52;
        const float* c = cost + d * STRD;
        float* p = P + d * STRD;
        float s = 0.f;
        for (int x = xs; x < xs + 52; x++) { if (x >= d) s += c[x]; p[x] = s; }
        segS[tid] = s;
    }
    __syncthreads();
    if (tid < 294 && seg > 0) {
        float off = 0.f;
        for (int q = 0; q < seg; q++) off += segS[d * 6 + q];
        float* p = P + d * STRD;
        for (int x = seg * 52; x < seg * 52 + 52; x++) p[x] += off;
    }
    __syncthreads();
}

__device__ __forceinline__ void get_ab(const int* prevv, const int* nextv, int x, int& a, int& b) {
    int Lr = x - prevv[x] - 1; if (Lr < 0) Lr = 0;
    int Rr = nextv[x] - x - 1; if (Rr < 0) Rr = 0;
    a = x - Lr; if (a < x - 12) a = x - 12;
    b = x + Rr; if (b > x + 12) b = x + 12;
    if (b > 311) b = 311;
}

__device__ __forceinline__ void issue_chunk(const float* Lrow, const float* Rrow,
                                            uint32_t sb, int tid, int k) {
    int buf = k % 3;
    if (tid < 312) {
        cp16(sb + OFF_LS + buf * 4992 + rot(tid),      Lrow + (size_t)tid * 384 + k * 4);
        cp16(sb + OFF_RS + buf * 5760 + rot(tid + 48), Rrow + (size_t)tid * 384 + k * 4);
    }
    asm volatile("cp.async.commit_group;\n" ::: "memory");
}

__global__ void __launch_bounds__(320, 1)
loss_row_kernel(const float* __restrict__ fL, const float* __restrict__ fR,
                const float* __restrict__ stu, float* __restrict__ out) {
    extern __shared__ __align__(128) char smem[];
    float* cost  = (float*)(smem + OFF_COST);
    float* P     = (float*)(smem + OFF_P);
    float* ent   = (float*)(smem + OFF_ENT);
    int*   prevv = (int*)(smem + OFF_PREV);
    int*   nextv = (int*)(smem + OFF_NEXT);
    float* segS  = (float*)(smem + OFF_SEG);
    float* redN  = (float*)(smem + OFF_RED);
    float* redC  = redN + 10;

    const int tid = threadIdx.x;
    const int row = blockIdx.x;
    const int b = row >> 5, h = 64 + (row & 31);
    const float* Lrow   = fL  + (size_t)(b * 96 + h) * (312 * 384);
    const float* Rrow   = fR  + (size_t)(b * 96 + h) * (312 * 384);
    const float* stuRow = stu + (size_t)(b * 96 + h) * 312;
    const uint32_t sb = (uint32_t)__cvta_generic_to_shared(smem);

    for (int t = tid; t < 3 * 48; t += 320) {            // zero R pads (x-d < 0)
        int buf = t / 48, j = t - buf * 48;
        *(float4*)(smem + OFF_RS + buf * 5760 + rot(j)) = make_float4(0.f, 0.f, 0.f, 0.f);
    }

    const int xg = tid / 7, dg = tid - xg * 7;
    const bool act = (tid < 273);
    const int x0 = xg * 8, dbase = dg * 7;
    const int J0 = x0 - dbase + 42;

    int lOff[8], rOff[14];
    #pragma unroll
    for (int i = 0; i < 8; i++)  lOff[i] = rot(x0 + i);
    #pragma unroll
    for (int m = 0; m < 14; m++) rOff[m] = rot(J0 + m);

    unsigned long long acc2[56];
    #pragma unroll
    for (int q = 0; q < 56; q++) acc2[q] = 0ULL;

    issue_chunk(Lrow, Rrow, sb, tid, 0);
    issue_chunk(Lrow, Rrow, sb, tid, 1);
    issue_chunk(Lrow, Rrow, sb, tid, 2);

    for (int k = 0; k < 96; k++) {
        asm volatile("cp.async.wait_group 2;\n" ::: "memory");
        __syncthreads();
        if (act) {
            int buf = k % 3;
            uint32_t lbase = sb + OFF_LS + buf * 4992;
            uint32_t rbase = sb + OFF_RS + buf * 5760;
            unsigned long long Lp[16];
            #pragma unroll
            for (int i = 0; i < 8; i++) {
                uint32_t a = lbase + lOff[i];
                Lp[2 * i] = lds64(a); Lp[2 * i + 1] = lds64h(a);
            }
            #pragma unroll
            for (int m = 0; m < 14; m++) {
                uint32_t a = rbase + rOff[m];
                unsigned long long r01 = lds64(a), r23 = lds64h(a);
                #pragma unroll
                for (int i = 0; i < 8; i++) {
                    const int dd = i - m + 6;
                    if (dd >= 0 && dd < 7) {
                        fma2(acc2[i * 7 + dd], Lp[2 * i], r01);
                        fma2(acc2[i * 7 + dd], Lp[2 * i + 1], r23);
                    }
                }
            }
        }
        __syncthreads();
        if (k + 3 < 96) issue_chunk(Lrow, Rrow, sb, tid, k + 3);
    }

    if (act)
        #pragma unroll
        for (int i = 0; i < 8; i++)
            #pragma unroll
            for (int dd = 0; dd < 7; dd++)
                cost[(dbase + dd) * STRD + (x0 + i)] = accsum(acc2[i * 7 + dd]);
    __syncthreads();

    // entropy ent0
    if (tid < 312) ent[tid] = col_entropy(cost, tid);
    __syncthreads();

    // stage-1: extents + prefix + refine + ent1
    extents(ent, prevv, nextv, tid);
    __syncthreads();
    prefix_scan(cost, P, segS, tid);
    if (tid < 157) {
        int x = 62 + tid;
        if (ent[x] > 0.6f) {
            int a, bb; get_ab(prevv, nextv, x, a, bb);
            float invd = 1.0f / (float)(bb - a + 1);
            for (int d = 0; d <= 48; d++)
                cost[d * STRD + x] = (P[d * STRD + bb] - P[d * STRD + a - 1]) * invd;
            ent[x] = col_entropy(cost, x);
        }
    }
    __syncthreads();

    // stage-2: extents + prefix + teacher + loss
    extents(ent, prevv, nextv, tid);
    __syncthreads();
    prefix_scan(cost, P, segS, tid);

    float lnum = 0.f, lcnt = 0.f;
    if (tid < 157) {
        int x = 62 + tid;
        if (ent[x] > 0.6f) {
            int a, bb; get_ab(prevv, nextv, x, a, bb);
            float best = -3.4e38f; int bd = 0;
            for (int d = 0; d <= 48; d++) {
                float nm = P[d * STRD + bb] - P[d * STRD + a - 1];
                if (nm > best) { best = nm; bd = d; }
            }
            float ad = fabsf(stuRow[x] * 0.25f - (float)bd);
            lnum = (ad < 1.f) ? 0.5f * ad * ad : ad - 0.5f;
            lcnt = 1.f;
        }
    }
    int wid = tid >> 5, lane = tid & 31;
    #pragma unroll
    for (int o = 16; o; o >>= 1) {
        lnum += __shfl_down_sync(0xffffffffu, lnum, o);
        lcnt += __shfl_down_sync(0xffffffffu, lcnt, o);
    }
    if (lane == 0) { redN[wid] = lnum; redC[wid] = lcnt; }
    __syncthreads();

    int* lastf = prevv;  // extents no longer needed
    if (tid == 0) {
        float n = 0.f, c = 0.f;
        for (int w = 0; w < 10; w++) { n += redN[w]; c += redC[w]; }
        g_row[row * 2] = n; g_row[row * 2 + 1] = c;
        __threadfence();
        unsigned o = atomicInc(&g_ticket, 127u);   // wraps to 0 each replay
        lastf[0] = (o == 127u);
    }
    __syncthreads();

    if (lastf[0] && tid < 32) {
        __threadfence();
        float acc = 0.f;
        if (tid < 4) {
            float n = 0.f, c = 0.f;
            for (int r = tid * 32; r < tid * 32 + 32; r++) {
                n += g_row[2 * r]; c += g_row[2 * r + 1];
            }
            acc = n / fmaxf(c, 1.f);
        }
        acc += __shfl_down_sync(0xffffffffu, acc, 2);
        acc += __shfl_down_sync(0xffffffffu, acc, 1);
        if (tid == 0) out[0] = acc * 0.25f;
    }
}

extern "C" void kernel_launch(void* const* d_in, const int* in_sizes, int n_in,
                              void* d_out, int out_size) {
    const float* fL  = (const float*)d_in[0];
    const float* fR  = (const float*)d_in[1];
    const float* stu = (const float*)d_in[2];
    cudaFuncSetAttribute(loss_row_kernel, cudaFuncAttributeMaxDynamicSharedMemorySize, SMEM_BYTES);
    loss_row_kernel<<<128, 320, SMEM_BYTES>>>(fL, fR, stu, (float*)d_out);
}

// round 9
// speedup vs baseline: 1.6451x; 1.6451x over previous
#include <cuda_runtime.h>
#include <cuda_bf16.h>
#include <cstdint>

#define STRD 313
#define OFF_LS   0          // 3 * 4992
#define OFF_RS   14976      // 3 * 7392 (padded R layout)
#define OFF_COST 37248
#define OFF_P    98688
#define OFF_ENT  160128
#define OFF_PREV 161408
#define OFF_NEXT 162688
#define OFF_SEG  163968
#define OFF_RED  165248
#define SMEM_BYTES 165376

__device__ float g_row[256];
__device__ unsigned g_ticket;

// L staging: per-128B-row slot rotation. Conflict-free across xg (stride 8),
// broadcast across dg (same address).
__device__ __forceinline__ int rotL(int j) {
    return (((j & ~7) | ((j + (j >> 3)) & 7)) << 4);
}
// R staging: padded layout, 2 pad units every 7. For the dg stride (dj=-7):
// dp = -9 == -1 (mod 8) -> 7 dg lanes hit 7 distinct bank groups.
__device__ __forceinline__ int padR(int j) {
    return ((j + 2 * (j / 7)) << 4);
}

__device__ __forceinline__ void cp16(uint32_t dst, const void* src) {
    asm volatile("cp.async.cg.shared.global [%0], [%1], 16;\n" :: "r"(dst), "l"(src));
}

__device__ __forceinline__ float col_entropy(const float* cost, int x) {
    int dmax = x < 48 ? x : 48;
    const float* c = cost + x;
    float m = c[0];
    for (int d = 1; d <= dmax; d++) m = fmaxf(m, c[d * STRD]);
    float S = 0.f;
    for (int d = 0; d <= dmax; d++) S += expf((c[d * STRD] - m) * 10.0f);
    float logS = logf(S), invS = 1.0f / S;
    float thr = logS - 18.420681f;
    float acc = 0.f;
    for (int d = 0; d <= dmax; d++) {
        float l = (c[d * STRD] - m) * 10.0f;
        if (l >= thr) { float p = expf(l) * invS; acc -= p * (l - logS); }
        else acc += 1.8420681e-7f;
    }
    acc += (float)(48 - dmax) * 1.8420681e-7f;
    if (dmax == 0) return 0.f;
    float e = acc / (logf((float)(dmax + 1)) + 1e-8f);
    return fminf(1.0f, fmaxf(0.0f, e));
}

__device__ __forceinline__ void extents(const float* ent, int* prevv, int* nextv, int tid) {
    int wid = tid >> 5, lane = tid & 31;
    if (wid == 0) {
        int carry = -1;
        for (int s = 0; s < 10; s++) {
            int idx = s * 32 + lane;
            int v = (idx < 312 && ent[idx] <= 0.6f) ? idx : -1;
            #pragma unroll
            for (int o = 1; o < 32; o <<= 1) {
                int t = __shfl_up_sync(0xffffffffu, v, o);
                if (lane >= o) v = max(v, t);
            }
            v = max(v, carry);
            if (idx < 312) prevv[idx] = v;
            carry = __shfl_sync(0xffffffffu, v, 31);
        }
    } else if (wid == 1) {
        int carry = 312;
        for (int s = 0; s < 10; s++) {
            int idx = 311 - (s * 32 + lane);
            int v = (idx >= 0 && ent[idx] <= 0.6f) ? idx : 312;
            #pragma unroll
            for (int o = 1; o < 32; o <<= 1) {
                int t = __shfl_up_sync(0xffffffffu, v, o);
                if (lane >= o) v = min(v, t);
            }
            v = min(v, carry);
            if (idx >= 0) nextv[idx] = v;
            carry = __shfl_sync(0xffffffffu, v, 31);
        }
    }
}

__device__ __forceinline__ void prefix_scan(const float* cost, float* P, float* segS, int tid) {
    int d = tid / 6, seg = tid - d * 6;
    if (tid < 294) {
        int xs = seg * 52;
        const float* c = cost + d * STRD;
        float* p = P + d * STRD;
        float s = 0.f;
        for (int x = xs; x < xs + 52; x++) { if (x >= d) s += c[x]; p[x] = s; }
        segS[tid] = s;
    }
    __syncthreads();
    if (tid < 294 && seg > 0) {
        float off = 0.f;
        for (int q = 0; q < seg; q++) off += segS[d * 6 + q];
        float* p = P + d * STRD;
        for (int x = seg * 52; x < seg * 52 + 52; x++) p[x] += off;
    }
    __syncthreads();
}

__device__ __forceinline__ void get_ab(const int* prevv, const int* nextv, int x, int& a, int& b) {
    int Lr = x - prevv[x] - 1; if (Lr < 0) Lr = 0;
    int Rr = nextv[x] - x - 1; if (Rr < 0) Rr = 0;
    a = x - Lr; if (a < x - 12) a = x - 12;
    b = x + Rr; if (b > x + 12) b = x + 12;
    if (b > 311) b = 311;
}

__device__ __forceinline__ void issue_chunk(const float* Lrow, const float* Rrow,
                                            uint32_t sb, int tid, int k, int rdst) {
    int buf = k % 3;
    if (tid < 312) {
        cp16(sb + OFF_LS + buf * 4992 + rotL(tid), Lrow + (size_t)tid * 384 + k * 4);
        cp16(sb + OFF_RS + buf * 7392 + rdst,      Rrow + (size_t)tid * 384 + k * 4);
    }
    asm volatile("cp.async.commit_group;\n" ::: "memory");
}

__global__ void __launch_bounds__(320, 1)
loss_row_kernel(const float* __restrict__ fL, const float* __restrict__ fR,
                const float* __restrict__ stu, float* __restrict__ out) {
    extern __shared__ __align__(128) char smem[];
    float* cost  = (float*)(smem + OFF_COST);
    float* P     = (float*)(smem + OFF_P);
    float* ent   = (float*)(smem + OFF_ENT);
    int*   prevv = (int*)(smem + OFF_PREV);
    int*   nextv = (int*)(smem + OFF_NEXT);
    float* segS  = (float*)(smem + OFF_SEG);
    float* redN  = (float*)(smem + OFF_RED);
    float* redC  = redN + 10;

    const int tid = threadIdx.x;
    const int row = blockIdx.x;
    const int b = row >> 5, h = 64 + (row & 31);
    const float* Lrow   = fL  + (size_t)(b * 96 + h) * (312 * 384);
    const float* Rrow   = fR  + (size_t)(b * 96 + h) * (312 * 384);
    const float* stuRow = stu + (size_t)(b * 96 + h) * 312;
    const uint32_t sb = (uint32_t)__cvta_generic_to_shared(smem);

    const int rdst = padR(tid + 48);               // per-thread R staging offset

    for (int t = tid; t < 3 * 48; t += 320) {      // zero R pads (x-d < 0)
        int buf = t / 48, j = t - buf * 48;
        *(float4*)(smem + OFF_RS + buf * 7392 + padR(j)) = make_float4(0.f, 0.f, 0.f, 0.f);
    }

    const int xg = tid / 7, dg = tid - xg * 7;
    const bool act = (tid < 273);                  // 39 x-groups * 7 d-groups
    const int x0 = xg * 8, dbase = dg * 7;
    const int J0 = x0 - dbase + 42;

    int lOff[8], rOff[14];
    #pragma unroll
    for (int i = 0; i < 8; i++)  lOff[i] = rotL(x0 + i);
    #pragma unroll
    for (int m = 0; m < 14; m++) rOff[m] = padR(J0 + m);

    float acc[8][7];
    #pragma unroll
    for (int i = 0; i < 8; i++)
        #pragma unroll
        for (int dd = 0; dd < 7; dd++) acc[i][dd] = 0.f;

    issue_chunk(Lrow, Rrow, sb, tid, 0, rdst);
    issue_chunk(Lrow, Rrow, sb, tid, 1, rdst);
    issue_chunk(Lrow, Rrow, sb, tid, 2, rdst);

    for (int k = 0; k < 96; k++) {
        asm volatile("cp.async.wait_group 2;\n" ::: "memory");
        __syncthreads();
        if (act) {
            int buf = k % 3;
            const char* lb = smem + OFF_LS + buf * 4992;
            const char* rb = smem + OFF_RS + buf * 7392;
            float4 Lv[8];
            #pragma unroll
            for (int i = 0; i < 8; i++) Lv[i] = *(const float4*)(lb + lOff[i]);
            #pragma unroll
            for (int m = 0; m < 14; m++) {
                float4 r = *(const float4*)(rb + rOff[m]);
                #pragma unroll
                for (int i = 0; i < 8; i++) {
                    const int dd = i - m + 6;
                    if (dd >= 0 && dd < 7) {
                        float a = acc[i][dd];
                        a = fmaf(Lv[i].x, r.x, a);
                        a = fmaf(Lv[i].y, r.y, a);
                        a = fmaf(Lv[i].z, r.z, a);
                        a = fmaf(Lv[i].w, r.w, a);
                        acc[i][dd] = a;
                    }
                }
            }
        }
        __syncthreads();
        if (k + 3 < 96) issue_chunk(Lrow, Rrow, sb, tid, k + 3, rdst);
    }

    if (act)
        #pragma unroll
        for (int i = 0; i < 8; i++)
            #pragma unroll
            for (int dd = 0; dd < 7; dd++)
                cost[(dbase + dd) * STRD + (x0 + i)] = acc[i][dd];
    __syncthreads();

    // entropy ent0
    if (tid < 312) ent[tid] = col_entropy(cost, tid);
    __syncthreads();

    // stage-1: extents + prefix + refine + ent1
    extents(ent, prevv, nextv, tid);
    __syncthreads();
    prefix_scan(cost, P, segS, tid);
    if (tid < 157) {
        int x = 62 + tid;
        if (ent[x] > 0.6f) {
            int a, bb; get_ab(prevv, nextv, x, a, bb);
            float invd = 1.0f / (float)(bb - a + 1);
            for (int d = 0; d <= 48; d++)
                cost[d * STRD + x] = (P[d * STRD + bb] - P[d * STRD + a - 1]) * invd;
            ent[x] = col_entropy(cost, x);
        }
    }
    __syncthreads();

    // stage-2: extents + prefix + teacher + loss
    extents(ent, prevv, nextv, tid);
    __syncthreads();
    prefix_scan(cost, P, segS, tid);

    float lnum = 0.f, lcnt = 0.f;
    if (tid < 157) {
        int x = 62 + tid;
        if (ent[x] > 0.6f) {
            int a, bb; get_ab(prevv, nextv, x, a, bb);
            float best = -3.4e38f; int bd = 0;
            for (int d = 0; d <= 48; d++) {
                float nm = P[d * STRD + bb] - P[d * STRD + a - 1];
                if (nm > best) { best = nm; bd = d; }
            }
            float ad = fabsf(stuRow[x] * 0.25f - (float)bd);
            lnum = (ad < 1.f) ? 0.5f * ad * ad : ad - 0.5f;
            lcnt = 1.f;
        }
    }
    int wid = tid >> 5, lane = tid & 31;
    #pragma unroll
    for (int o = 16; o; o >>= 1) {
        lnum += __shfl_down_sync(0xffffffffu, lnum, o);
        lcnt += __shfl_down_sync(0xffffffffu, lcnt, o);
    }
    if (lane == 0) { redN[wid] = lnum; redC[wid] = lcnt; }
    __syncthreads();

    int* lastf = prevv;
    if (tid == 0) {
        float n = 0.f, c = 0.f;
        for (int w = 0; w < 10; w++) { n += redN[w]; c += redC[w]; }
        g_row[row * 2] = n; g_row[row * 2 + 1] = c;
        __threadfence();
        unsigned o = atomicInc(&g_ticket, 127u);   // wraps to 0 each replay
        lastf[0] = (o == 127u);
    }
    __syncthreads();

    if (lastf[0] && tid < 32) {
        __threadfence();
        float acc1 = 0.f;
        if (tid < 4) {
            float n = 0.f, c = 0.f;
            for (int r = tid * 32; r < tid * 32 + 32; r++) {
                n += g_row[2 * r]; c += g_row[2 * r + 1];
            }
            acc1 = n / fmaxf(c, 1.f);
        }
        acc1 += __shfl_down_sync(0xffffffffu, acc1, 2);
        acc1 += __shfl_down_sync(0xffffffffu, acc1, 1);
        if (tid == 0) out[0] = acc1 * 0.25f;
    }
}

extern "C" void kernel_launch(void* const* d_in, const int* in_sizes, int n_in,
                              void* d_out, int out_size) {
    const float* fL  = (const float*)d_in[0];
    const float* fR  = (const float*)d_in[1];
    const float* stu = (const float*)d_in[2];
    cudaFuncSetAttribute(loss_row_kernel, cudaFuncAttributeMaxDynamicSharedMemorySize, SMEM_BYTES);
    loss_row_kernel<<<128, 320, SMEM_BYTES>>>(fL, fR, stu, (float*)d_out);
}